// round 9
// baseline (speedup 1.0000x reference)
#include <cuda_runtime.h>
#include <math.h>

#define B_     256
#define T_     1024
#define DIN    32
#define DH     200
#define DOUT   2
#define CHUNK  32
#define NCHUNK (T_ / CHUNK)
#define NTHR   192          // 4 producer warps + consumer warp (4 or 5) + 1 idle
#define NPROD  128
#define NACT   100          // threads 0..99 each own units 2t, 2t+1
#define PADR   101          // float2 row stride for partials (conflict degree 2)

#define XS_BYTES  (CHUNK * DIN * 4)                   // 4096 per slot, 3 slots
#define PART_F2   (CHUNK * PADR)                      // 3232 float2 per buffer
#define OFF_XS    0
#define OFF_PART  (3 * XS_BYTES)                      // 12288
#define OFF_MBAR  (OFF_PART + 2 * PART_F2 * 8)        // 64000
#define SMEM_TOTAL (OFF_MBAR + 64)

__device__ __forceinline__ unsigned sm_u32(const void* p) {
    return (unsigned)__cvta_generic_to_shared(p);
}
__device__ __forceinline__ void cp16(unsigned saddr, const void* g) {
    asm volatile("cp.async.ca.shared.global [%0], [%1], 16;" :: "r"(saddr), "l"(g));
}
__device__ __forceinline__ unsigned long long pack2(float x, float y) {
    unsigned long long v;
    asm("mov.b64 %0, {%1, %2};" : "=l"(v) : "f"(x), "f"(y));
    return v;
}
__device__ __forceinline__ void fma2(unsigned long long& d,
                                     unsigned long long a, unsigned long long b) {
    asm("fma.rn.f32x2 %0, %1, %2, %0;" : "+l"(d) : "l"(a), "l"(b));
}
__device__ __forceinline__ float sum2(unsigned long long a, unsigned long long b) {
    unsigned long long s;
    asm("add.rn.f32x2 %0, %1, %2;" : "=l"(s) : "l"(a), "l"(b));
    float lo, hi;
    asm("mov.b64 {%0, %1}, %2;" : "=f"(lo), "=f"(hi) : "l"(s));
    return lo + hi;
}
__device__ __forceinline__ void mbar_init(unsigned a, unsigned cnt) {
    asm volatile("mbarrier.init.shared.b64 [%0], %1;" :: "r"(a), "r"(cnt));
}
__device__ __forceinline__ void mbar_arrive(unsigned a) {
    asm volatile("mbarrier.arrive.release.cta.shared::cta.b64 _, [%0];" :: "r"(a) : "memory");
}
__device__ __forceinline__ void mbar_wait(unsigned a, unsigned parity) {
    asm volatile(
        "{\n\t.reg .pred P;\n\t"
        "WL_%=:\n\t"
        "mbarrier.try_wait.parity.acquire.cta.shared::cta.b64 P, [%0], %1, 0x989680;\n\t"
        "@P bra.uni WD_%=;\n\t"
        "bra.uni WL_%=;\n\t"
        "WD_%=:\n\t}"
        :: "r"(a), "r"(parity) : "memory");
}

__global__ __launch_bounds__(NTHR, 2)
void snn_kernel(const float* __restrict__ x,  const float* __restrict__ W1,
                const float* __restrict__ b1, const float* __restrict__ W2,
                const float* __restrict__ b2, float* __restrict__ out,
                float a1, float a2)
{
    extern __shared__ __align__(16) unsigned char smem_raw[];
    float2* part = (float2*)(smem_raw + OFF_PART);
    const unsigned smem_base = sm_u32(smem_raw);
    const unsigned xs_sa = smem_base + OFF_XS;
    const unsigned mbF0 = smem_base + OFF_MBAR;
    const unsigned mbF1 = mbF0 + 8;
    const unsigned mbE0 = mbF0 + 16;
    const unsigned mbE1 = mbF0 + 24;

    const int b   = blockIdx.x;
    const int tid = threadIdx.x;
    const int wid = tid >> 5;
    // consumer warp: 4 or 5, chosen so co-resident CTA pairs (b, b+148)
    // put their consumers on different SMSPs (bit 7 differs within a pair)
    const int cwid = 4 + ((b >> 7) & 1);

    // output layout: output[B,2] | s1s[B,T,DH] | m1s[B,T,DH] | s2s[B,T,2] | m2s[B,T,2]
    float* out_o  = out;
    float* out_s1 = out + (size_t)B_ * DOUT;
    float* out_m1 = out_s1 + (size_t)B_ * T_ * DH;
    float* out_s2 = out_m1 + (size_t)B_ * T_ * DH;
    float* out_m2 = out_s2 + (size_t)B_ * T_ * DOUT;

    const float* xrow = x + (size_t)b * T_ * DIN;
    float* s1p = out_s1 + (size_t)b * T_ * DH;
    float* m1p = out_m1 + (size_t)b * T_ * DH;
    float* s2p = out_s2 + (size_t)b * T_ * DOUT;
    float* m2p = out_m2 + (size_t)b * T_ * DOUT;

    if (tid == 0) {
        mbar_init(mbF0, 4); mbar_init(mbF1, 4);   // one arrive per producer warp
        mbar_init(mbE0, 1); mbar_init(mbE1, 1);   // one elected consumer arrive
    }

    // ---- producer weights: 2 units per thread, W1 columns packed over k-pairs ----
    unsigned long long wpA[DIN / 2], wpB[DIN / 2];
    float w20A = 0.f, w21A = 0.f, w20B = 0.f, w21B = 0.f;
    unsigned long long accInitA = 0, accInitB = 0;
    const unsigned long long zero64 = pack2(0.f, 0.f);
    const bool lact = (tid < NACT);
    const int j0 = 2 * tid;
    if (lact) {
        #pragma unroll
        for (int kk = 0; kk < DIN / 2; kk++) {
            wpA[kk] = pack2(W1[(2 * kk) * DH + j0],     W1[(2 * kk + 1) * DH + j0]);
            wpB[kk] = pack2(W1[(2 * kk) * DH + j0 + 1], W1[(2 * kk + 1) * DH + j0 + 1]);
        }
        w20A = W2[j0 * 2 + 0];       w21A = W2[j0 * 2 + 1];
        w20B = W2[(j0 + 1) * 2 + 0]; w21B = W2[(j0 + 1) * 2 + 1];
        accInitA = pack2(b1[j0], 0.f);
        accInitB = pack2(b1[j0 + 1], 0.f);
    }
    __syncthreads();   // publish mbarrier init

    if (tid < NPROD) {
        // ================= PRODUCERS (layer 1) =================
        cp16(xs_sa + 0 * XS_BYTES + tid * 32,      xrow + tid * 8);
        cp16(xs_sa + 0 * XS_BYTES + tid * 32 + 16, xrow + tid * 8 + 4);
        asm volatile("cp.async.commit_group;");
        cp16(xs_sa + 1 * XS_BYTES + tid * 32,      xrow + CHUNK * DIN + tid * 8);
        cp16(xs_sa + 1 * XS_BYTES + tid * 32 + 16, xrow + CHUNK * DIN + tid * 8 + 4);
        asm volatile("cp.async.commit_group;");

        float m1A = 0.f, m1B = 0.f;

        for (int ch = 0; ch < NCHUNK; ch++) {
            if (ch + 1 < NCHUNK)
                asm volatile("cp.async.wait_group 1;");
            else
                asm volatile("cp.async.wait_group 0;");
            asm volatile("bar.sync 5, 128;" ::: "memory");  // x ready; reads of ch-1 retired

            if (ch + 2 < NCHUNK) {
                const float* g = xrow + (size_t)(ch + 2) * CHUNK * DIN + tid * 8;
                const unsigned s = xs_sa + ((ch + 2) % 3) * XS_BYTES + tid * 32;
                cp16(s, g);
                cp16(s + 16, g + 4);
            }
            asm volatile("cp.async.commit_group;");

            const int buf = ch & 1;
            const int u   = ch >> 1;
            if (ch >= 2)
                mbar_wait(buf ? mbE1 : mbE0, (unsigned)((u & 1) ^ 1));

            if (lact) {
                const unsigned xbase = xs_sa + (ch % 3) * XS_BYTES;
                float*  pS = s1p + (size_t)ch * CHUNK * DH + j0;
                float*  pM = m1p + (size_t)ch * CHUNK * DH + j0;
                float2* pP = part + (size_t)buf * PART_F2 + tid;
                #pragma unroll 4
                for (int tt = 0; tt < CHUNK; tt++) {
                    unsigned long long a0 = accInitA, a1r = zero64;
                    unsigned long long bb0 = accInitB, bb1 = zero64;
                    const unsigned xa0 = xbase + tt * (DIN * 4);
                    #pragma unroll
                    for (int q = 0; q < DIN / 4; q++) {
                        unsigned long long xa, xb;
                        asm("ld.shared.v2.b64 {%0, %1}, [%2];"
                            : "=l"(xa), "=l"(xb) : "r"(xa0 + q * 16));
                        fma2(a0,  xa, wpA[2 * q]);
                        fma2(a1r, xb, wpA[2 * q + 1]);
                        fma2(bb0, xa, wpB[2 * q]);
                        fma2(bb1, xb, wpB[2 * q + 1]);
                    }
                    const float driveA = sum2(a0, a1r);
                    const float driveB = sum2(bb0, bb1);
                    m1A = fmaf(m1A, a1, driveA);
                    const float s1A = (m1A > 0.5f) ? 1.0f : 0.0f;
                    m1A = fmaf(s1A, -0.5f, m1A);
                    m1B = fmaf(m1B, a1, driveB);
                    const float s1B = (m1B > 0.5f) ? 1.0f : 0.0f;
                    m1B = fmaf(s1B, -0.5f, m1B);

                    __stcs((float2*)pS, make_float2(s1A, s1B));  pS += DH;
                    __stcs((float2*)pM, make_float2(m1A, m1B));  pM += DH;
                    // pre-summed layer-2 partial: one float2 per thread per step
                    float px = s1A * w20A; px = fmaf(s1B, w20B, px);
                    float py = s1A * w21A; py = fmaf(s1B, w21B, py);
                    *pP = make_float2(px, py);
                    pP += PADR;
                }
            }
            __syncwarp();
            if ((tid & 31) == 0)
                mbar_arrive(buf ? mbF1 : mbF0);   // release covers warp's stores
        }
    } else if (wid == cwid) {
        // ================= CONSUMER (layer 2) =================
        const int lane = tid & 31;                // lane = timestep within chunk
        const float b2x = b2[0], b2y = b2[1];
        float m2x = 0.f, m2y = 0.f, os0 = 0.f, os1 = 0.f;
        float f0 = 0.f, f1 = 0.f;                 // m2s[t=0] per channel

        for (int ch = 0; ch < NCHUNK; ch++) {
            const int buf = ch & 1;
            const int u   = ch >> 1;
            mbar_wait(buf ? mbF1 : mbF0, (unsigned)(u & 1));

            // lane tt sums 100 pre-reduced float2 partials for its step
            const float2* pf = part + (size_t)buf * PART_F2 + lane * PADR;
            float ax0 = 0.f, ay0 = 0.f, ax1 = 0.f, ay1 = 0.f;
            #pragma unroll 4
            for (int j = 0; j < NACT; j += 2) {
                float2 v0 = pf[j], v1 = pf[j + 1];
                ax0 += v0.x; ay0 += v0.y;
                ax1 += v1.x; ay1 += v1.y;
            }
            const float sx = ax0 + ax1;           // drive for output 0, step=lane
            const float sy = ay0 + ay1;           // drive for output 1, step=lane

            __syncwarp();
            if (lane == 0)
                mbar_arrive(buf ? mbE1 : mbE0);   // part[buf] free once gathered

            // hoist all shuffles out of the serial chain
            float rA[CHUNK], rB[CHUNK];
            #pragma unroll
            for (int t2 = 0; t2 < CHUNK; t2++) {
                rA[t2] = __shfl_sync(0xffffffffu, sx, t2) + b2x;
                rB[t2] = __shfl_sync(0xffffffffu, sy, t2) + b2y;
            }

            // tight serial recurrence, both channels in-lane; lane t2 captures step t2
            float capS0 = 0.f, capS1 = 0.f, capM0 = 0.f, capM1 = 0.f;
            #pragma unroll
            for (int t2 = 0; t2 < CHUNK; t2++) {
                m2x = fmaf(m2x, a2, rA[t2]);
                const float sA = (m2x > 1.0f) ? 1.0f : 0.0f;
                m2x -= sA;
                m2y = fmaf(m2y, a2, rB[t2]);
                const float sB = (m2y > 1.0f) ? 1.0f : 0.0f;
                m2y -= sB;
                os0 += m2x; os1 += m2y;
                if (lane == t2) { capS0 = sA; capS1 = sB; capM0 = m2x; capM1 = m2y; }
            }
            // coalesced per-step stores: lane t2 <-> global step ch*CHUNK + t2
            const int gt = ch * CHUNK + lane;
            __stcs((float2*)(s2p + (size_t)gt * DOUT), make_float2(capS0, capS1));
            __stcs((float2*)(m2p + (size_t)gt * DOUT), make_float2(capM0, capM1));

            if (ch == 0) {                         // remember m2s[t=0] (lane 0's capture)
                f0 = __shfl_sync(0xffffffffu, capM0, 0);
                f1 = __shfl_sync(0xffffffffu, capM1, 0);
            }
        }
        if (lane == 0) {
            out_o[b * DOUT + 0] = (os0 - f0) * (1.0f / (float)T_);
            out_o[b * DOUT + 1] = (os1 - f1) * (1.0f / (float)T_);
        }
    }
    // warp (4 or 5) that is neither producer nor consumer simply exits
}

extern "C" void kernel_launch(void* const* d_in, const int* in_sizes, int n_in,
                              void* d_out, int out_size) {
    const float* x  = (const float*)d_in[0];
    const float* W1 = (const float*)d_in[1];
    const float* b1 = (const float*)d_in[2];
    const float* W2 = (const float*)d_in[3];
    const float* b2 = (const float*)d_in[4];

    const float a1 = (float)exp((double)(-1.0f / 10.0f));
    const float a2 = (float)exp((double)(-1.0f / 20.0f));

    cudaFuncSetAttribute(snn_kernel,
                         cudaFuncAttributeMaxDynamicSharedMemorySize, SMEM_TOTAL);
    snn_kernel<<<B_, NTHR, SMEM_TOTAL>>>(x, W1, b1, W2, b2, (float*)d_out, a1, a2);
}

// round 12
// speedup vs baseline: 1.0407x; 1.0407x over previous
#include <cuda_runtime.h>
#include <math.h>

#define B_     256
#define T_     1024
#define DIN    32
#define DH     200
#define DOUT   2
#define CHUNK  32
#define NCHUNK (T_ / CHUNK)
#define NTHR   160          // 4 producer warps + 1 consumer warp
#define NPROD  128
#define NACT   100          // threads 0..99 each own units 2t, 2t+1
#define PADR   101          // float2 row stride for partials (conflict degree 2)

#define XS_BYTES  (CHUNK * DIN * 4)                   // 4096 per slot, 3 slots
#define PART_F2   (CHUNK * PADR)                      // 3232 float2 per buffer
#define OFF_XS    0
#define OFF_PART  (3 * XS_BYTES)                      // 12288
#define OFF_MBAR  (OFF_PART + 2 * PART_F2 * 8)        // 64000
#define SMEM_TOTAL (OFF_MBAR + 64)

__device__ __forceinline__ unsigned sm_u32(const void* p) {
    return (unsigned)__cvta_generic_to_shared(p);
}
__device__ __forceinline__ void cp16(unsigned saddr, const void* g) {
    asm volatile("cp.async.ca.shared.global [%0], [%1], 16;" :: "r"(saddr), "l"(g));
}
__device__ __forceinline__ unsigned long long pack2(float x, float y) {
    unsigned long long v;
    asm("mov.b64 %0, {%1, %2};" : "=l"(v) : "f"(x), "f"(y));
    return v;
}
__device__ __forceinline__ void fma2(unsigned long long& d,
                                     unsigned long long a, unsigned long long b) {
    asm("fma.rn.f32x2 %0, %1, %2, %0;" : "+l"(d) : "l"(a), "l"(b));
}
__device__ __forceinline__ float sum2(unsigned long long a, unsigned long long b) {
    unsigned long long s;
    asm("add.rn.f32x2 %0, %1, %2;" : "=l"(s) : "l"(a), "l"(b));
    float lo, hi;
    asm("mov.b64 {%0, %1}, %2;" : "=f"(lo), "=f"(hi) : "l"(s));
    return lo + hi;
}
// Full 128-byte step load: 16 u64 = 32 floats. volatile + memory clobber so it
// can never cross the publish barrier.
__device__ __forceinline__ void ld16v(unsigned long long* xr, unsigned addr) {
    asm volatile(
        "ld.shared.v2.b64 {%0, %1}, [%16];\n\t"
        "ld.shared.v2.b64 {%2, %3}, [%17];\n\t"
        "ld.shared.v2.b64 {%4, %5}, [%18];\n\t"
        "ld.shared.v2.b64 {%6, %7}, [%19];\n\t"
        "ld.shared.v2.b64 {%8, %9}, [%20];\n\t"
        "ld.shared.v2.b64 {%10, %11}, [%21];\n\t"
        "ld.shared.v2.b64 {%12, %13}, [%22];\n\t"
        "ld.shared.v2.b64 {%14, %15}, [%23];"
        : "=l"(xr[0]),  "=l"(xr[1]),  "=l"(xr[2]),  "=l"(xr[3]),
          "=l"(xr[4]),  "=l"(xr[5]),  "=l"(xr[6]),  "=l"(xr[7]),
          "=l"(xr[8]),  "=l"(xr[9]),  "=l"(xr[10]), "=l"(xr[11]),
          "=l"(xr[12]), "=l"(xr[13]), "=l"(xr[14]), "=l"(xr[15])
        : "r"(addr),      "r"(addr + 16), "r"(addr + 32), "r"(addr + 48),
          "r"(addr + 64), "r"(addr + 80), "r"(addr + 96), "r"(addr + 112)
        : "memory");
}
__device__ __forceinline__ void mbar_init(unsigned a, unsigned cnt) {
    asm volatile("mbarrier.init.shared.b64 [%0], %1;" :: "r"(a), "r"(cnt));
}
__device__ __forceinline__ void mbar_arrive(unsigned a) {
    asm volatile("mbarrier.arrive.release.cta.shared::cta.b64 _, [%0];" :: "r"(a) : "memory");
}
__device__ __forceinline__ void mbar_wait(unsigned a, unsigned parity) {
    asm volatile(
        "{\n\t.reg .pred P;\n\t"
        "WL_%=:\n\t"
        "mbarrier.try_wait.parity.acquire.cta.shared::cta.b64 P, [%0], %1, 0x989680;\n\t"
        "@P bra.uni WD_%=;\n\t"
        "bra.uni WL_%=;\n\t"
        "WD_%=:\n\t}"
        :: "r"(a), "r"(parity) : "memory");
}

__global__ __launch_bounds__(NTHR, 2)
void snn_kernel(const float* __restrict__ x,  const float* __restrict__ W1,
                const float* __restrict__ b1, const float* __restrict__ W2,
                const float* __restrict__ b2, float* __restrict__ out,
                float a1, float a2)
{
    extern __shared__ __align__(16) unsigned char smem_raw[];
    float2* part = (float2*)(smem_raw + OFF_PART);
    const unsigned smem_base = sm_u32(smem_raw);
    const unsigned xs_sa = smem_base + OFF_XS;
    const unsigned mbF0 = smem_base + OFF_MBAR;
    const unsigned mbF1 = mbF0 + 8;
    const unsigned mbE0 = mbF0 + 16;
    const unsigned mbE1 = mbF0 + 24;

    const int b   = blockIdx.x;
    const int tid = threadIdx.x;

    // output layout: output[B,2] | s1s[B,T,DH] | m1s[B,T,DH] | s2s[B,T,2] | m2s[B,T,2]
    float* out_o  = out;
    float* out_s1 = out + (size_t)B_ * DOUT;
    float* out_m1 = out_s1 + (size_t)B_ * T_ * DH;
    float* out_s2 = out_m1 + (size_t)B_ * T_ * DH;
    float* out_m2 = out_s2 + (size_t)B_ * T_ * DOUT;

    const float* xrow = x + (size_t)b * T_ * DIN;
    float* s1p = out_s1 + (size_t)b * T_ * DH;
    float* m1p = out_m1 + (size_t)b * T_ * DH;
    float* s2p = out_s2 + (size_t)b * T_ * DOUT;
    float* m2p = out_m2 + (size_t)b * T_ * DOUT;

    if (tid == 0) {
        mbar_init(mbF0, 4); mbar_init(mbF1, 4);   // one arrive per producer warp
        mbar_init(mbE0, 1); mbar_init(mbE1, 1);   // one elected consumer arrive
    }

    // ---- producer weights: 2 units per thread, W1 columns packed over k-pairs ----
    unsigned long long wpA[DIN / 2], wpB[DIN / 2];
    float w20A = 0.f, w21A = 0.f, w20B = 0.f, w21B = 0.f;
    unsigned long long accInitA = 0, accInitB = 0;
    const unsigned long long zero64 = pack2(0.f, 0.f);
    const bool lact = (tid < NACT);
    const int j0 = 2 * tid;
    if (lact) {
        #pragma unroll
        for (int kk = 0; kk < DIN / 2; kk++) {
            wpA[kk] = pack2(W1[(2 * kk) * DH + j0],     W1[(2 * kk + 1) * DH + j0]);
            wpB[kk] = pack2(W1[(2 * kk) * DH + j0 + 1], W1[(2 * kk + 1) * DH + j0 + 1]);
        }
        w20A = W2[j0 * 2 + 0];       w21A = W2[j0 * 2 + 1];
        w20B = W2[(j0 + 1) * 2 + 0]; w21B = W2[(j0 + 1) * 2 + 1];
        accInitA = pack2(b1[j0], 0.f);
        accInitB = pack2(b1[j0 + 1], 0.f);
    }
    __syncthreads();   // publish mbarrier init

    if (tid < NPROD) {
        // ================= PRODUCERS (layer 1) =================
        cp16(xs_sa + 0 * XS_BYTES + tid * 32,      xrow + tid * 8);
        cp16(xs_sa + 0 * XS_BYTES + tid * 32 + 16, xrow + tid * 8 + 4);
        asm volatile("cp.async.commit_group;");
        cp16(xs_sa + 1 * XS_BYTES + tid * 32,      xrow + CHUNK * DIN + tid * 8);
        cp16(xs_sa + 1 * XS_BYTES + tid * 32 + 16, xrow + CHUNK * DIN + tid * 8 + 4);
        asm volatile("cp.async.commit_group;");

        float m1A = 0.f, m1B = 0.f;

        for (int ch = 0; ch < NCHUNK; ch++) {
            if (ch + 1 < NCHUNK)
                asm volatile("cp.async.wait_group 1;");
            else
                asm volatile("cp.async.wait_group 0;");
            asm volatile("bar.sync 5, 128;" ::: "memory");  // x ready; reads of ch-1 retired

            if (ch + 2 < NCHUNK) {
                const float* g = xrow + (size_t)(ch + 2) * CHUNK * DIN + tid * 8;
                const unsigned s = xs_sa + ((ch + 2) % 3) * XS_BYTES + tid * 32;
                cp16(s, g);
                cp16(s + 16, g + 4);
            }
            asm volatile("cp.async.commit_group;");

            const int buf = ch & 1;
            const int u   = ch >> 1;
            if (ch >= 2)
                mbar_wait(buf ? mbE1 : mbE0, (unsigned)((u & 1) ^ 1));

            if (lact) {
                const unsigned xbase = xs_sa + (ch % 3) * XS_BYTES;
                float*  pS = s1p + (size_t)ch * CHUNK * DH + j0;
                float*  pM = m1p + (size_t)ch * CHUNK * DH + j0;
                float2* pP = part + (size_t)buf * PART_F2 + tid;

                // one-full-step-ahead pipeline, explicit named buffers (16 u64 each)
                unsigned long long x0[16], x1[16];
                ld16v(x0, xbase);                     // step 0

                for (int tt = 0; tt < CHUNK; tt += 2) {
                    // ---- step tt (data in x0); prefetch tt+1 into x1 first ----
                    ld16v(x1, xbase + (tt + 1) * (DIN * 4));
                    {
                        unsigned long long a0 = accInitA, a1r = zero64;
                        unsigned long long bb0 = accInitB, bb1 = zero64;
                        #pragma unroll
                        for (int q = 0; q < DIN / 4; q++) {
                            fma2(a0,  x0[2 * q],     wpA[2 * q]);
                            fma2(a1r, x0[2 * q + 1], wpA[2 * q + 1]);
                            fma2(bb0, x0[2 * q],     wpB[2 * q]);
                            fma2(bb1, x0[2 * q + 1], wpB[2 * q + 1]);
                        }
                        const float driveA = sum2(a0, a1r);
                        const float driveB = sum2(bb0, bb1);
                        m1A = fmaf(m1A, a1, driveA);
                        const float s1A = (m1A > 0.5f) ? 1.0f : 0.0f;
                        m1A = fmaf(s1A, -0.5f, m1A);
                        m1B = fmaf(m1B, a1, driveB);
                        const float s1B = (m1B > 0.5f) ? 1.0f : 0.0f;
                        m1B = fmaf(s1B, -0.5f, m1B);

                        __stcs((float2*)pS, make_float2(s1A, s1B));  pS += DH;
                        __stcs((float2*)pM, make_float2(m1A, m1B));  pM += DH;
                        float px = s1A * w20A; px = fmaf(s1B, w20B, px);
                        float py = s1A * w21A; py = fmaf(s1B, w21B, py);
                        *pP = make_float2(px, py);
                        pP += PADR;
                    }
                    // ---- step tt+1 (data in x1); prefetch tt+2 into x0 first ----
                    if (tt + 2 < CHUNK)
                        ld16v(x0, xbase + (tt + 2) * (DIN * 4));
                    {
                        unsigned long long a0 = accInitA, a1r = zero64;
                        unsigned long long bb0 = accInitB, bb1 = zero64;
                        #pragma unroll
                        for (int q = 0; q < DIN / 4; q++) {
                            fma2(a0,  x1[2 * q],     wpA[2 * q]);
                            fma2(a1r, x1[2 * q + 1], wpA[2 * q + 1]);
                            fma2(bb0, x1[2 * q],     wpB[2 * q]);
                            fma2(bb1, x1[2 * q + 1], wpB[2 * q + 1]);
                        }
                        const float driveA = sum2(a0, a1r);
                        const float driveB = sum2(bb0, bb1);
                        m1A = fmaf(m1A, a1, driveA);
                        const float s1A = (m1A > 0.5f) ? 1.0f : 0.0f;
                        m1A = fmaf(s1A, -0.5f, m1A);
                        m1B = fmaf(m1B, a1, driveB);
                        const float s1B = (m1B > 0.5f) ? 1.0f : 0.0f;
                        m1B = fmaf(s1B, -0.5f, m1B);

                        __stcs((float2*)pS, make_float2(s1A, s1B));  pS += DH;
                        __stcs((float2*)pM, make_float2(m1A, m1B));  pM += DH;
                        float px = s1A * w20A; px = fmaf(s1B, w20B, px);
                        float py = s1A * w21A; py = fmaf(s1B, w21B, py);
                        *pP = make_float2(px, py);
                        pP += PADR;
                    }
                }
            }
            __syncwarp();
            if ((tid & 31) == 0)
                mbar_arrive(buf ? mbF1 : mbF0);   // release covers warp's stores
        }
    } else {
        // ================= CONSUMER (layer 2) =================
        const int lane = tid - NPROD;             // lane = timestep within chunk
        const float b2x = b2[0], b2y = b2[1];
        float m2x = 0.f, m2y = 0.f, os0 = 0.f, os1 = 0.f;
        float f0 = 0.f, f1 = 0.f;                 // m2s[t=0] per channel

        for (int ch = 0; ch < NCHUNK; ch++) {
            const int buf = ch & 1;
            const int u   = ch >> 1;
            mbar_wait(buf ? mbF1 : mbF0, (unsigned)(u & 1));

            // lane tt sums 100 pre-reduced float2 partials for its step
            const float2* pf = part + (size_t)buf * PART_F2 + lane * PADR;
            float ax0 = 0.f, ay0 = 0.f, ax1 = 0.f, ay1 = 0.f;
            #pragma unroll 4
            for (int j = 0; j < NACT; j += 2) {
                float2 v0 = pf[j], v1 = pf[j + 1];
                ax0 += v0.x; ay0 += v0.y;
                ax1 += v1.x; ay1 += v1.y;
            }
            const float sx = ax0 + ax1;           // drive for output 0, step=lane
            const float sy = ay0 + ay1;           // drive for output 1, step=lane

            __syncwarp();
            if (lane == 0)
                mbar_arrive(buf ? mbE1 : mbE0);   // part[buf] free once gathered

            // hoist all shuffles out of the serial chain
            float rA[CHUNK], rB[CHUNK];
            #pragma unroll
            for (int t2 = 0; t2 < CHUNK; t2++) {
                rA[t2] = __shfl_sync(0xffffffffu, sx, t2) + b2x;
                rB[t2] = __shfl_sync(0xffffffffu, sy, t2) + b2y;
            }

            // tight serial recurrence, both channels in-lane; lane t2 captures step t2
            float capS0 = 0.f, capS1 = 0.f, capM0 = 0.f, capM1 = 0.f;
            #pragma unroll
            for (int t2 = 0; t2 < CHUNK; t2++) {
                m2x = fmaf(m2x, a2, rA[t2]);
                const float sA = (m2x > 1.0f) ? 1.0f : 0.0f;
                m2x -= sA;
                m2y = fmaf(m2y, a2, rB[t2]);
                const float sB = (m2y > 1.0f) ? 1.0f : 0.0f;
                m2y -= sB;
                os0 += m2x; os1 += m2y;
                if (lane == t2) { capS0 = sA; capS1 = sB; capM0 = m2x; capM1 = m2y; }
            }
            // coalesced per-step stores: lane t2 <-> global step ch*CHUNK + t2
            const int gt = ch * CHUNK + lane;
            __stcs((float2*)(s2p + (size_t)gt * DOUT), make_float2(capS0, capS1));
            __stcs((float2*)(m2p + (size_t)gt * DOUT), make_float2(capM0, capM1));

            if (ch == 0) {                         // remember m2s[t=0] (lane 0's capture)
                f0 = __shfl_sync(0xffffffffu, capM0, 0);
                f1 = __shfl_sync(0xffffffffu, capM1, 0);
            }
        }
        if (lane == 0) {
            out_o[b * DOUT + 0] = (os0 - f0) * (1.0f / (float)T_);
            out_o[b * DOUT + 1] = (os1 - f1) * (1.0f / (float)T_);
        }
    }
}

extern "C" void kernel_launch(void* const* d_in, const int* in_sizes, int n_in,
                              void* d_out, int out_size) {
    const float* x  = (const float*)d_in[0];
    const float* W1 = (const float*)d_in[1];
    const float* b1 = (const float*)d_in[2];
    const float* W2 = (const float*)d_in[3];
    const float* b2 = (const float*)d_in[4];

    const float a1 = (float)exp((double)(-1.0f / 10.0f));
    const float a2 = (float)exp((double)(-1.0f / 20.0f));

    cudaFuncSetAttribute(snn_kernel,
                         cudaFuncAttributeMaxDynamicSharedMemorySize, SMEM_TOTAL);
    snn_kernel<<<B_, NTHR, SMEM_TOTAL>>>(x, W1, b1, W2, b2, (float*)d_out, a1, a2);
}